// round 16
// baseline (speedup 1.0000x reference)
#include <cuda_runtime.h>

#define MAXN 100000
#define MAXE 1000000
#define F 64

// Scratch (__device__ globals only; never take their address in host code —
// GB300 ATS silently routes host-shadow addresses over NVLink-C2C, R6 lesson).
// g_degi invariant: zero at entry to every executed kernel_launch.
__device__ int   g_degi[MAXN];
__device__ int   g_pre[MAXN];     // block-exclusive prefix of degrees
__device__ int   g_bsum[256];
__device__ int   g_rowptr[MAXN];  // row start
__device__ int   g_cursor[MAXN];  // after fill: row end (rowptr + deg)
__device__ int   g_csrc[MAXE];
__device__ float g_hs1[(size_t)MAXN * F];
__device__ float g_hs2[(size_t)MAXN * F];

__global__ void k_deg_count(const int* __restrict__ dst, int E) {
    int e = blockIdx.x * blockDim.x + threadIdx.x;
    if (e < E) atomicAdd(&g_degi[dst[e]], 1);
}

__global__ void k_deg_zero(int N) {
    int i = blockIdx.x * blockDim.x + threadIdx.x;
    if (i < N) g_degi[i] = 0;
}

// ---- CSR build ----
__global__ void k_scan1(int N) {
    __shared__ int s[512];
    int t = threadIdx.x;
    int i = blockIdx.x * 512 + t;
    int d = (i < N) ? g_degi[i] : 0;
    s[t] = d;
    __syncthreads();
#pragma unroll
    for (int o = 1; o < 512; o <<= 1) {
        int a = (t >= o) ? s[t - o] : 0;
        __syncthreads();
        s[t] += a;
        __syncthreads();
    }
    if (i < N) g_pre[i] = s[t] - d;   // block-exclusive prefix
    if (t == 511) g_bsum[blockIdx.x] = s[511];
}

__global__ void k_scan23(int N, int NB) {
    __shared__ int red[512];
    int b = blockIdx.x;
    int t = threadIdx.x;
    red[t] = (t < b && t < NB) ? g_bsum[t] : 0;
    __syncthreads();
#pragma unroll
    for (int o = 256; o > 0; o >>= 1) {
        if (t < o) red[t] += red[t + o];
        __syncthreads();
    }
    int off = red[0];
    int i = b * 512 + t;
    if (i < N) {
        int start = off + g_pre[i];
        g_rowptr[i] = start;
        g_cursor[i] = start;
    }
}

__global__ void k_fill(const int* __restrict__ src, const int* __restrict__ dst, int E) {
    int e = blockIdx.x * blockDim.x + threadIdx.x;
    if (e >= E) return;
    int p = atomicAdd(&g_cursor[dst[e]], 1);
    g_csrc[p] = src[e];
}

// ---- Layer-1 GEMM: hs1 = (x@W1)*dinv, dinv inline from degi ----
__global__ void __launch_bounds__(256, 3)
k_gemm1(const float* __restrict__ xin, const float* __restrict__ W, int N) {
    constexpr int TM = 4, TN = 8, CPT = F / TN, RPB = (256 / CPT) * TM;  // 128
    __shared__ float sW[F * F];
    {
        const float4* W4 = (const float4*)W;
        float4* sW4 = (float4*)sW;
        for (int i = threadIdx.x; i < F * F / 4; i += 256) sW4[i] = W4[i];
    }
    __syncthreads();

    int q  = threadIdx.x % CPT;
    int gl = threadIdx.x / CPT;
    int row0 = blockIdx.x * RPB + gl * TM;
    if (row0 >= N) return;

    float acc[TM][TN];
#pragma unroll
    for (int r = 0; r < TM; r++)
#pragma unroll
        for (int j = 0; j < TN; j++) acc[r][j] = 0.0f;

    float dv[TM];
#pragma unroll
    for (int r = 0; r < TM; r++) {
        int row = row0 + r;
        dv[r] = (row < N) ? rsqrtf(1.0f + (float)g_degi[row]) : 0.0f;
    }

#pragma unroll
    for (int kk = 0; kk < F / 4; kk++) {
        float xr[TM][4];
#pragma unroll
        for (int r = 0; r < TM; r++) {
            int row = row0 + r;
            float4 a = make_float4(0.f, 0.f, 0.f, 0.f);
            if (row < N) a = *(const float4*)&xin[(size_t)row * F + kk * 4];
            xr[r][0] = a.x; xr[r][1] = a.y; xr[r][2] = a.z; xr[r][3] = a.w;
        }
#pragma unroll
        for (int u = 0; u < 4; u++) {
            const float4* wr = (const float4*)&sW[(kk * 4 + u) * F + q * TN];
            float4 w0 = wr[0], w1 = wr[1];
#pragma unroll
            for (int r = 0; r < TM; r++) {
                float v = xr[r][u];
                acc[r][0] = fmaf(v, w0.x, acc[r][0]);
                acc[r][1] = fmaf(v, w0.y, acc[r][1]);
                acc[r][2] = fmaf(v, w0.z, acc[r][2]);
                acc[r][3] = fmaf(v, w0.w, acc[r][3]);
                acc[r][4] = fmaf(v, w1.x, acc[r][4]);
                acc[r][5] = fmaf(v, w1.y, acc[r][5]);
                acc[r][6] = fmaf(v, w1.z, acc[r][6]);
                acc[r][7] = fmaf(v, w1.w, acc[r][7]);
            }
        }
    }

#pragma unroll
    for (int r = 0; r < TM; r++) {
        int row = row0 + r;
        if (row >= N) break;
        float4* h4 = (float4*)(g_hs1 + (size_t)row * F + q * TN);
        float4 r0, r1;
        r0.x = acc[r][0] * dv[r];  r0.y = acc[r][1] * dv[r];
        r0.z = acc[r][2] * dv[r];  r0.w = acc[r][3] * dv[r];
        r1.x = acc[r][4] * dv[r];  r1.y = acc[r][5] * dv[r];
        r1.z = acc[r][6] * dv[r];  r1.w = acc[r][7] * dv[r];
        h4[0] = r0; h4[1] = r1;
    }
}

// ---- Fused gather+GEMM. Stage 1: per-node acc = hs[n] + sum_neigh hs[s],
// then relu(dinv*acc + b) into smem. Stage 2: register-blocked GEMM from smem.
// XS = 68 floats: row stride 272 B -> 16B-aligned (float4 ok), 68 mod 32 = 4
// -> rows land on distinct bank groups (conflict-free stage 2 reads).
//  L=1: in=hs1, result -> g_hs2 = (in@W)*dinv     (NOUT=64, TM=4)
//  L=2: in=hs2, result -> out  = in@W + b_out     (NOUT=32, TM=2)
template <int NOUT, int L>
__global__ void __launch_bounds__(256)
k_fused(const float* __restrict__ W, const float* __restrict__ b_in,
        const float* __restrict__ b_out, float* __restrict__ out, int N) {
    constexpr int TN = 8;
    constexpr int CPT = NOUT / TN;              // 8 or 4
    constexpr int TM  = (NOUT == 64) ? 4 : 2;   // 256 threads cover 128 rows
    constexpr int RPB = 128;
    constexpr int XS  = 68;                     // smem row stride (floats)

    extern __shared__ float smem[];
    float* sW = smem;               // F*NOUT
    float* sX = sW + F * NOUT;      // RPB*XS  (slot 64 = dv)

    const float* hs = (L == 1) ? g_hs1 : g_hs2;
    int base = blockIdx.x * RPB;

    // load W (stage 2 operand; ordered by the single __syncthreads below)
    {
        const float4* W4 = (const float4*)W;
        float4* sW4 = (float4*)sW;
        for (int i = threadIdx.x; i < F * NOUT / 4; i += 256) sW4[i] = W4[i];
    }

    // stage 1: gather 128 rows x 16 float4-chunks (16 threads per row)
#pragma unroll
    for (int i = 0; i < RPB * 16 / 256; i++) {   // 8 iterations
        int task = i * 256 + threadIdx.x;
        int nl   = task >> 4;
        int c    = (task & 15) * 4;
        int node = base + nl;
        if (node < N) {
            float4 a = *(const float4*)&hs[(size_t)node * F + c];
            int rp = g_rowptr[node];
            int re = g_cursor[node];
            int j = rp;
            for (; j + 1 < re; j += 2) {
                int s0 = g_csrc[j];
                int s1 = g_csrc[j + 1];
                float4 v0 = *(const float4*)&hs[(size_t)s0 * F + c];
                float4 v1 = *(const float4*)&hs[(size_t)s1 * F + c];
                a.x += v0.x; a.y += v0.y; a.z += v0.z; a.w += v0.w;
                a.x += v1.x; a.y += v1.y; a.z += v1.z; a.w += v1.w;
            }
            if (j < re) {
                int s0 = g_csrc[j];
                float4 v0 = *(const float4*)&hs[(size_t)s0 * F + c];
                a.x += v0.x; a.y += v0.y; a.z += v0.z; a.w += v0.w;
            }
            float dv = rsqrtf(1.0f + (float)(re - rp));
            float4 bb = *(const float4*)&b_in[c];
            float4 val;
            val.x = fmaxf(fmaf(dv, a.x, bb.x), 0.0f);
            val.y = fmaxf(fmaf(dv, a.y, bb.y), 0.0f);
            val.z = fmaxf(fmaf(dv, a.z, bb.z), 0.0f);
            val.w = fmaxf(fmaf(dv, a.w, bb.w), 0.0f);
            *(float4*)&sX[nl * XS + c] = val;
            if (c == 0) sX[nl * XS + 64] = dv;
        }
    }
    __syncthreads();

    // stage 2: GEMM from sX
    int q  = threadIdx.x % CPT;
    int gl = threadIdx.x / CPT;
    int rl0 = gl * TM;                 // local row
    int row0 = base + rl0;
    if (row0 >= N) return;

    float acc[TM][TN];
#pragma unroll
    for (int r = 0; r < TM; r++)
#pragma unroll
        for (int j = 0; j < TN; j++) acc[r][j] = 0.0f;

#pragma unroll
    for (int kk = 0; kk < F / 4; kk++) {
        float xr[TM][4];
#pragma unroll
        for (int r = 0; r < TM; r++) {
            float4 a = *(const float4*)&sX[(rl0 + r) * XS + kk * 4];
            xr[r][0] = a.x; xr[r][1] = a.y; xr[r][2] = a.z; xr[r][3] = a.w;
        }
#pragma unroll
        for (int u = 0; u < 4; u++) {
            const float4* wr = (const float4*)&sW[(kk * 4 + u) * NOUT + q * TN];
            float4 w0 = wr[0], w1 = wr[1];
#pragma unroll
            for (int r = 0; r < TM; r++) {
                float v = xr[r][u];
                acc[r][0] = fmaf(v, w0.x, acc[r][0]);
                acc[r][1] = fmaf(v, w0.y, acc[r][1]);
                acc[r][2] = fmaf(v, w0.z, acc[r][2]);
                acc[r][3] = fmaf(v, w0.w, acc[r][3]);
                acc[r][4] = fmaf(v, w1.x, acc[r][4]);
                acc[r][5] = fmaf(v, w1.y, acc[r][5]);
                acc[r][6] = fmaf(v, w1.z, acc[r][6]);
                acc[r][7] = fmaf(v, w1.w, acc[r][7]);
            }
        }
    }

    if (L == 2) {
        const float4* bo4 = (const float4*)(b_out + q * TN);
        float4 bo0 = bo4[0], bo1 = bo4[1];
#pragma unroll
        for (int r = 0; r < TM; r++) {
            int row = row0 + r;
            if (row >= N) break;
            float4* o4 = (float4*)(out + (size_t)row * NOUT + q * TN);
            float4 r0, r1;
            r0.x = acc[r][0] + bo0.x;  r0.y = acc[r][1] + bo0.y;
            r0.z = acc[r][2] + bo0.z;  r0.w = acc[r][3] + bo0.w;
            r1.x = acc[r][4] + bo1.x;  r1.y = acc[r][5] + bo1.y;
            r1.z = acc[r][6] + bo1.z;  r1.w = acc[r][7] + bo1.w;
            o4[0] = r0; o4[1] = r1;
        }
    } else {
#pragma unroll
        for (int r = 0; r < TM; r++) {
            int row = row0 + r;
            if (row >= N) break;
            float dvr = sX[(rl0 + r) * XS + 64];
            float4* h4 = (float4*)(g_hs2 + (size_t)row * F + q * TN);
            float4 r0, r1;
            r0.x = acc[r][0] * dvr;  r0.y = acc[r][1] * dvr;
            r0.z = acc[r][2] * dvr;  r0.w = acc[r][3] * dvr;
            r1.x = acc[r][4] * dvr;  r1.y = acc[r][5] * dvr;
            r1.z = acc[r][6] * dvr;  r1.w = acc[r][7] * dvr;
            h4[0] = r0; h4[1] = r1;
        }
    }
}

extern "C" void kernel_launch(void* const* d_in, const int* in_sizes, int n_in,
                              void* d_out, int out_size) {
    const float* x  = (const float*)d_in[0];
    const int*   ei = (const int*)d_in[1];
    const float* W1 = (const float*)d_in[2];
    const float* b1 = (const float*)d_in[3];
    const float* W2 = (const float*)d_in[4];
    const float* b2 = (const float*)d_in[5];
    const float* Wl = (const float*)d_in[6];
    const float* bl = (const float*)d_in[7];
    float* out = (float*)d_out;

    int N = in_sizes[0] / F;
    int E = in_sizes[1] / 2;
    const int* src = ei;
    const int* dst = ei + E;

    int nb256 = (N + 255) / 256;
    int eb    = (E + 255) / 256;
    int nbs   = (N + 511) / 512;
    int fb    = (N + 127) / 128;   // 128 rows/block for gemm1 + fused

    int smB = (F * 64 + 128 * 68) * (int)sizeof(float);   // 51200 B
    int smC = (F * 32 + 128 * 68) * (int)sizeof(float);   // 43008 B
    cudaFuncSetAttribute(k_fused<64, 1>, cudaFuncAttributeMaxDynamicSharedMemorySize, smB);
    cudaFuncSetAttribute(k_fused<32, 2>, cudaFuncAttributeMaxDynamicSharedMemorySize, smC);

    // Fork/join stream (created fresh each call; intentionally not destroyed —
    // can't destroy a forked stream mid-capture; handful of calls per process).
    cudaStream_t s2;
    cudaStreamCreateWithFlags(&s2, cudaStreamNonBlocking);
    cudaEvent_t evDeg, evCsr, evG1, evZero;
    cudaEventCreateWithFlags(&evDeg, cudaEventDisableTiming);
    cudaEventCreateWithFlags(&evCsr, cudaEventDisableTiming);
    cudaEventCreateWithFlags(&evG1, cudaEventDisableTiming);
    cudaEventCreateWithFlags(&evZero, cudaEventDisableTiming);

    // degree (g_degi zero at entry by invariant)
    k_deg_count<<<eb, 256>>>(dst, E);
    cudaEventRecord(evDeg, 0);

    // s2: CSR build (reads degi only in scan1)
    cudaStreamWaitEvent(s2, evDeg, 0);
    k_scan1<<<nbs, 512, 0, s2>>>(N);
    k_scan23<<<nbs, 512, 0, s2>>>(N, nbs);
    k_fill<<<eb, 256, 0, s2>>>(src, dst, E);
    cudaEventRecord(evCsr, s2);

    // main: gemm1 (reads degi for inline dinv)
    k_gemm1<<<fb, 256>>>(x, W1, N);
    cudaEventRecord(evG1, 0);

    // s2: restore degi=0 invariant after its last readers (scan1, gemm1)
    cudaStreamWaitEvent(s2, evG1, 0);
    k_deg_zero<<<nb256, 256, 0, s2>>>(N);
    cudaEventRecord(evZero, s2);

    // main: fused layer 2 (gather(hs1)+relu+GEMM -> hs2), then fused head
    cudaStreamWaitEvent(0, evCsr, 0);
    k_fused<64, 1><<<fb, 256, smB>>>(W2, b1, nullptr, nullptr, N);
    k_fused<32, 2><<<fb, 256, smC>>>(Wl, b2, bl, out, N);

    // join: zeroing must be inside the captured graph
    cudaStreamWaitEvent(0, evZero, 0);
}